// round 1
// baseline (speedup 1.0000x reference)
#include <cuda_runtime.h>
#include <cuda_bf16.h>

// Problem constants
#define QN   16384      // B*N queries
#define DD   256        // dim
#define KK   8192       // codebook size
#define TM   128        // query tile
#define TN   128        // code tile
#define KT   32         // k-chunk per stage
#define NTHREADS 256
#define SPLITS 8        // code-dim splits -> grid 128x8 = 1024 blocks
#define CODES_PER_BLOCK (KK / SPLITS)      // 1024
#define CT_PER_BLOCK    (CODES_PER_BLOCK / TN)   // 8
#define NSTAGES  (CT_PER_BLOCK * (DD / KT))      // 64
#define SMEM_A_FLOATS (TM * DD)                  // 32768 floats = 128KB
#define SMEM_B_FLOATS (3 * TN * KT)              // 12288 floats = 48KB
#define SMEM_BYTES ((SMEM_A_FLOATS + SMEM_B_FLOATS) * 4)

typedef unsigned long long ull;

__device__ ull   g_minkey[QN];
__device__ float g_c2[KK];

__device__ __forceinline__ unsigned f2ord(float f) {
    unsigned u = __float_as_uint(f);
    return (u & 0x80000000u) ? ~u : (u | 0x80000000u);
}

__device__ __forceinline__ void cp16(float* smem_dst, const float* gsrc) {
    unsigned s = (unsigned)__cvta_generic_to_shared(smem_dst);
    asm volatile("cp.async.cg.shared.global [%0], [%1], 16;\n" :: "r"(s), "l"(gsrc));
}
__device__ __forceinline__ void cp_commit() {
    asm volatile("cp.async.commit_group;\n" ::: "memory");
}
__device__ __forceinline__ void cp_wait1() {
    asm volatile("cp.async.wait_group 1;\n" ::: "memory");
}

// packed fp32x2 FMA: c += a*b elementwise on two packed floats (Blackwell FFMA2)
#define FMA2(c, a, b) asm volatile("fma.rn.f32x2 %0, %1, %2, %0;\n" : "+l"(c) : "l"(a), "l"(b))

// ---------------------------------------------------------------------------
// Kernel 1: codebook row norms + minkey init
// ---------------------------------------------------------------------------
__global__ void vq_prep(const float* __restrict__ cb) {
    int t = blockIdx.x * blockDim.x + threadIdx.x;   // 0..8191
    if (t < KK) {
        const float4* r = (const float4*)(cb + (size_t)t * DD);
        float s = 0.f;
#pragma unroll 16
        for (int i = 0; i < DD / 4; i++) {
            float4 v = r[i];
            s += v.x * v.x + v.y * v.y + v.z * v.z + v.w * v.w;
        }
        g_c2[t] = s;
    }
    if (t < QN) g_minkey[t] = 0xFFFFFFFFFFFFFFFFull;
    if (t + KK < QN) g_minkey[t + KK] = 0xFFFFFFFFFFFFFFFFull;
}

// ---------------------------------------------------------------------------
// Kernel 2: fused distance GEMM + argmin.  dist = c2[k] - 2*dot(q,c)
// grid: (SPLITS, QN/TM), block 256 threads.
// A (queries 128x256) resident in smem; B (codes 128x32) 3-deep cp.async ring.
// ---------------------------------------------------------------------------
extern __shared__ float dyn_smem[];

__global__ void __launch_bounds__(NTHREADS, 1)
vq_main(const float* __restrict__ x, const float* __restrict__ cb) {
    float* As = dyn_smem;                       // [128][256] plain layout
    float* Bs = dyn_smem + SMEM_A_FLOATS;       // 3 x [128][32] swizzled

    const int tid = threadIdx.x;
    const int tx  = tid & 15;                   // n-group 0..15 (8 codes each)
    const int ty  = tid >> 4;                   // m-group 0..15 (8 queries each)
    const int qbase = blockIdx.y * TM;
    const int cbase = blockIdx.x * CODES_PER_BLOCK;

    // ---- load resident query tile (128KB), plain coalesced float4 ----
    {
        const float4* xg = (const float4*)(x + (size_t)qbase * DD);
        float4* As4 = (float4*)As;
#pragma unroll
        for (int i = 0; i < (TM * DD / 4) / NTHREADS; i++)
            As4[tid + i * NTHREADS] = xg[tid + i * NTHREADS];
    }

    // ---- B-stage issue: stage s = (ct<<3)|kst, buffer s%3, XOR-swizzled ----
    auto issueB = [&](int s) {
        int buf = s % 3, ct = s >> 3, kst = s & 7;
        float* Bbuf = Bs + buf * (TN * KT);
        const float* gB = cb + (size_t)(cbase + ct * TN) * DD + kst * KT;
#pragma unroll
        for (int j = 0; j < 4; j++) {
            int l  = tid + NTHREADS * j;        // 0..1023 float4 slots
            int n  = l >> 3;                    // code row 0..127
            int k4 = l & 7;                     // float4 col within KT
            int sidx4 = n * 8 + (k4 ^ ((n >> 3) & 7));
            cp16(Bbuf + sidx4 * 4, gB + n * DD + k4 * 4);
        }
    };

    ull acc[8][8];
#pragma unroll
    for (int i = 0; i < 8; i++)
#pragma unroll
        for (int j = 0; j < 8; j++) acc[i][j] = 0ull;

    ull best[8];
#pragma unroll
    for (int i = 0; i < 8; i++) best[i] = 0xFFFFFFFFFFFFFFFFull;

    issueB(0); cp_commit();
    issueB(1); cp_commit();

    const ulonglong2* Ad = (const ulonglong2*)As;   // 16B units; row = 64 units
    const int swz = tx & 7;

    for (int s = 0; s < NSTAGES; s++) {
        cp_wait1();                 // stage s data landed
        __syncthreads();            // visible to all; prior compute done
        if (s + 2 < NSTAGES) issueB(s + 2);
        cp_commit();                // commit (possibly empty) to keep counts

        const int buf = s % 3, kst = s & 7;
        const ulonglong2* Bd = (const ulonglong2*)(Bs + buf * (TN * KT));

#pragma unroll
        for (int k4 = 0; k4 < 8; k4++) {
            const int col = kst * 8 + k4;
            ulonglong2 aa[8], bb[8];
#pragma unroll
            for (int im = 0; im < 8; im++)
                aa[im] = Ad[(ty * 8 + im) * 64 + col];
#pragma unroll
            for (int jn = 0; jn < 8; jn++)
                bb[jn] = Bd[(tx * 8 + jn) * 8 + (k4 ^ swz)];
#pragma unroll
            for (int im = 0; im < 8; im++)
#pragma unroll
                for (int jn = 0; jn < 8; jn++) {
                    FMA2(acc[im][jn], aa[im].x, bb[jn].x);
                    FMA2(acc[im][jn], aa[im].y, bb[jn].y);
                }
        }

        if ((s & 7) == 7) {         // finished full-D for this code tile
            const int ct = s >> 3;
            const int nb = cbase + ct * TN + tx * 8;
#pragma unroll
            for (int im = 0; im < 8; im++) {
                ull bk = 0xFFFFFFFFFFFFFFFFull;
#pragma unroll
                for (int jn = 0; jn < 8; jn++) {
                    ull a = acc[im][jn];
                    float lo = __int_as_float((int)(unsigned)(a & 0xFFFFFFFFull));
                    float hi = __int_as_float((int)(unsigned)(a >> 32));
                    float dot = lo + hi;
                    float dist = fmaf(-2.0f, dot, g_c2[nb + jn]);
                    ull key = ((ull)f2ord(dist) << 32) | (ull)(unsigned)(nb + jn);
                    bk = (key < bk) ? key : bk;
                    acc[im][jn] = 0ull;
                }
                // reduce across the 16 lanes (tx) sharing these 8 query rows
#pragma unroll
                for (int off = 8; off; off >>= 1) {
                    ull o = __shfl_xor_sync(0xFFFFFFFFu, bk, off);
                    bk = (o < bk) ? o : bk;
                }
                best[im] = (bk < best[im]) ? bk : best[im];
            }
        }
    }

    if (tx == 0) {
#pragma unroll
        for (int im = 0; im < 8; im++)
            atomicMin(&g_minkey[qbase + ty * 8 + im], best[im]);
    }
}

// ---------------------------------------------------------------------------
// Kernel 3: gather + write outputs [x_recon | z_e | z_q | indices(float)]
// ---------------------------------------------------------------------------
__global__ void vq_out(const float* __restrict__ x, const float* __restrict__ cb,
                       float* __restrict__ out, int out_size) {
    const int BND  = QN * DD;         // 4194304
    const int BND4 = BND / 4;         // 1048576
    int t = blockIdx.x * blockDim.x + threadIdx.x;
    if (t >= BND4) return;
    int q  = t >> 6;                  // query row
    int c4 = t & 63;                  // float4 col
    unsigned idx = (unsigned)(g_minkey[q] & 0xFFFFFFFFull);
    float4 zq = ((const float4*)cb)[(size_t)idx * 64 + c4];
    float4 xv = ((const float4*)x)[t];
    float4* o4 = (float4*)out;
    if (out_size >= BND)     o4[t] = zq;                 // x_recon
    if (out_size >= 2 * BND) o4[BND4 + t] = xv;          // z_e
    if (out_size >= 3 * BND) o4[2 * BND4 + t] = zq;      // z_q
    if (c4 == 0 && out_size >= 3 * BND + QN)
        out[3 * BND + q] = (float)idx;                   // indices
}

// ---------------------------------------------------------------------------
extern "C" void kernel_launch(void* const* d_in, const int* in_sizes, int n_in,
                              void* d_out, int out_size) {
    const float* x  = (const float*)d_in[0];   // (8,2048,256) f32
    const float* cb = (const float*)d_in[1];   // (8192,256)  f32
    float* out = (float*)d_out;

    cudaFuncSetAttribute(vq_main, cudaFuncAttributeMaxDynamicSharedMemorySize,
                         SMEM_BYTES);

    vq_prep<<<KK / NTHREADS, NTHREADS>>>(cb);
    dim3 grid(SPLITS, QN / TM);
    vq_main<<<grid, NTHREADS, SMEM_BYTES>>>(x, cb);
    vq_out<<<(QN * DD / 4 + NTHREADS - 1) / NTHREADS, NTHREADS>>>(x, cb, out, out_size);
}

// round 3
// speedup vs baseline: 1.9522x; 1.9522x over previous
#include <cuda_runtime.h>
#include <cuda_bf16.h>
#include <cstdint>

// ---------------------------------------------------------------------------
// Problem constants
// ---------------------------------------------------------------------------
#define QN 16384      // B*N queries
#define DD 256        // dim
#define KK 8192       // codebook size
#define TM 128        // queries per block
#define TN 128        // codes per tile
#define NTILES (KK / TN)          // 64
#define NSTAGES (NTILES * 8)      // 512 (per tile: 4 k-chunks x {hi,lo})
#define NTHREADS 256
#define RESCORE_T 0.05f

// smem layout (bytes): A_hi 64K | A_lo 64K | B ring 4x16K | c2 32K = 224KB
#define SM_A_HI 0
#define SM_A_LO 65536
#define SM_BRING 131072
#define SM_C2 196608
#define SM_TOTAL 229376

typedef unsigned long long ull;

// ---------------------------------------------------------------------------
// device scratch (static: no allocations allowed)
// ---------------------------------------------------------------------------
__device__ __nv_bfloat16 g_x_hi[QN * DD];
__device__ __nv_bfloat16 g_x_lo[QN * DD];
__device__ __nv_bfloat16 g_cb_hi[KK * DD];
__device__ __nv_bfloat16 g_cb_lo[KK * DD];
__device__ float    g_c2[KK];
__device__ unsigned g_idx[QN];

// ---------------------------------------------------------------------------
// PTX helpers (all sm_80-baseline: legal on plain sm_103 target)
// ---------------------------------------------------------------------------
__device__ __forceinline__ unsigned smem_u32(const void* p) {
    unsigned a;
    asm("{ .reg .u64 t; cvta.to.shared.u64 t, %1; cvt.u32.u64 %0, t; }" : "=r"(a) : "l"(p));
    return a;
}
__device__ __forceinline__ void cp16(unsigned sdst, const void* g) {
    asm volatile("cp.async.cg.shared.global [%0], [%1], 16;" :: "r"(sdst), "l"(g));
}
#define CP_COMMIT() asm volatile("cp.async.commit_group;" ::: "memory")
#define CP_WAIT2()  asm volatile("cp.async.wait_group 2;" ::: "memory")
#define CP_WAIT0()  asm volatile("cp.async.wait_group 0;" ::: "memory")

__device__ __forceinline__ void ldsm4(unsigned* r, unsigned addr) {
    asm volatile("ldmatrix.sync.aligned.m8n8.x4.shared.b16 {%0,%1,%2,%3}, [%4];"
                 : "=r"(r[0]), "=r"(r[1]), "=r"(r[2]), "=r"(r[3]) : "r"(addr));
}
__device__ __forceinline__ void mma16816(float* c, const unsigned* a, const unsigned* b) {
    asm volatile("mma.sync.aligned.m16n8k16.row.col.f32.bf16.bf16.f32 "
                 "{%0,%1,%2,%3}, {%4,%5,%6,%7}, {%8,%9}, {%0,%1,%2,%3};"
                 : "+f"(c[0]), "+f"(c[1]), "+f"(c[2]), "+f"(c[3])
                 : "r"(a[0]), "r"(a[1]), "r"(a[2]), "r"(a[3]), "r"(b[0]), "r"(b[1]));
}

__device__ __forceinline__ unsigned f2ord(float f) {
    unsigned u = __float_as_uint(f);
    return (u & 0x80000000u) ? ~u : (u | 0x80000000u);
}
__device__ __forceinline__ void upd2(ull& k1, ull& k2, ull k) {
    if (k < k1) { k2 = k1; k1 = k; } else if (k < k2) { k2 = k; }
}

// ---------------------------------------------------------------------------
// Kernel: fp32 -> bf16 hi/lo split (elementwise, coalesced)
// ---------------------------------------------------------------------------
__device__ __forceinline__ unsigned pack2(__nv_bfloat16 a, __nv_bfloat16 b) {
    __nv_bfloat162 p = __halves2bfloat162(a, b);
    return *reinterpret_cast<unsigned*>(&p);
}

__global__ void vq_cvt(const float* __restrict__ x, const float* __restrict__ cb) {
    const int QX4 = QN * DD / 4, TOT4 = (QN + KK) * DD / 4;
    int t = blockIdx.x * blockDim.x + threadIdx.x;
    if (t >= TOT4) return;
    bool isx = t < QX4;
    float4 v = isx ? ((const float4*)x)[t] : ((const float4*)cb)[t - QX4];
    float vv[4] = {v.x, v.y, v.z, v.w};
    __nv_bfloat16 h[4], l[4];
#pragma unroll
    for (int i = 0; i < 4; i++) {
        h[i] = __float2bfloat16_rn(vv[i]);
        l[i] = __float2bfloat16_rn(vv[i] - __bfloat162float(h[i]));
    }
    uint2 hp = make_uint2(pack2(h[0], h[1]), pack2(h[2], h[3]));
    uint2 lp = make_uint2(pack2(l[0], l[1]), pack2(l[2], l[3]));
    int o = isx ? t : t - QX4;
    ((uint2*)(isx ? g_x_hi : g_cb_hi))[o] = hp;
    ((uint2*)(isx ? g_x_lo : g_cb_lo))[o] = lp;
}

// ---------------------------------------------------------------------------
// Kernel: codebook row norms (one warp per row)
// ---------------------------------------------------------------------------
__global__ void vq_c2k(const float* __restrict__ cb) {
    int w = (blockIdx.x * blockDim.x + threadIdx.x) >> 5;
    int lane = threadIdx.x & 31;
    if (w >= KK) return;
    const float4* r = (const float4*)(cb + (size_t)w * DD);
    float s = 0.f;
#pragma unroll
    for (int j = 0; j < 2; j++) {
        float4 v = r[lane + 32 * j];
        s += v.x * v.x + v.y * v.y + v.z * v.z + v.w * v.w;
    }
#pragma unroll
    for (int o = 16; o; o >>= 1) s += __shfl_xor_sync(0xFFFFFFFFu, s, o);
    if (!lane) g_c2[w] = s;
}

// ---------------------------------------------------------------------------
// Main kernel: mma.sync bf16 split-3 GEMM + fused best-2 argmin + fp32 rescore
// grid = 128 blocks (one per 128-query tile), 256 threads = 8 compute warps.
// Each warp: m16 (16 queries) x n128 (full code tile), 64 fp32 accums.
// B streamed in 16KB chunks (128 codes x 64 k) via 4-deep cp.async ring.
// ---------------------------------------------------------------------------
extern __shared__ char dsm[];

__device__ __forceinline__ float dot_exact(const float* a, const float* b) {
    float s0 = 0, s1 = 0, s2 = 0, s3 = 0;
    const float4* A = (const float4*)a;
    const float4* B = (const float4*)b;
#pragma unroll 16
    for (int i = 0; i < DD / 4; i++) {
        float4 u = A[i], w = B[i];
        s0 = fmaf(u.x, w.x, s0); s1 = fmaf(u.y, w.y, s1);
        s2 = fmaf(u.z, w.z, s2); s3 = fmaf(u.w, w.w, s3);
    }
    return (s0 + s1) + (s2 + s3);
}

__global__ void __launch_bounds__(NTHREADS, 1)
vq_main_mma(const float* __restrict__ x, const float* __restrict__ cb) {
    const unsigned sb = smem_u32(dsm);
    const int tid = threadIdx.x;
    const int warp = tid >> 5, lane = tid & 31;
    const int qbase = blockIdx.x * TM;

    // ---- stage issue: s = tile*8 + kc*2 + half ----
    auto issueB = [&](int s) {
        const int tile = s >> 3, kc = (s & 7) >> 1, half = s & 1;
        const __nv_bfloat16* src = half ? g_cb_lo : g_cb_hi;
        const unsigned stage = sb + SM_BRING + (s & 3) * 16384;
#pragma unroll
        for (int i = 0; i < 4; i++) {
            int unit = tid + i * NTHREADS;          // 0..1023
            int row = unit >> 3, u = unit & 7;
            cp16(stage + row * 128 + ((u ^ (row & 7)) << 4),
                 src + (size_t)(tile * TN + row) * DD + kc * 64 + u * 8);
        }
    };

    // ---- group 0: resident A_hi/A_lo (swizzled) + c2 ----
#pragma unroll
    for (int i = 0; i < 32; i++) {
        int l = i * NTHREADS + tid;                 // 0..8191 16B units
        int half = l >> 12;                         // 0: hi, 1: lo
        int w = l & 4095;
        int row = w >> 5, u = w & 31;
        int su = (u & 24) | ((u ^ row) & 7);
        const __nv_bfloat16* src = half ? g_x_lo : g_x_hi;
        cp16(sb + (half ? SM_A_LO : SM_A_HI) + row * 512 + (su << 4),
             src + (size_t)(qbase + row) * DD + u * 8);
    }
#pragma unroll
    for (int i = 0; i < 8; i++) {
        int l = i * NTHREADS + tid;                 // 0..2047
        cp16(sb + SM_C2 + l * 16, g_c2 + l * 4);
    }
    CP_COMMIT();
    issueB(0); CP_COMMIT();
    issueB(1); CP_COMMIT();
    issueB(2); CP_COMMIT();

    // ldmatrix lane address components
    const int a_row = warp * 16 + (lane & 7) + ((lane >> 3) & 1) * 8;
    const int a_uoff = (lane >> 4) & 1;
    const int b_rowp = (lane & 7) + ((lane >> 4) & 1) * 8;
    const int b_uoff = (lane >> 3) & 1;

    const float* c2s = (const float*)(dsm + SM_C2);

    ull k1lo = ~0ull, k2lo = ~0ull, k1hi = ~0ull, k2hi = ~0ull;

    int s = 0;
    for (int t = 0; t < NTILES; t++) {
        float acc[16][4];
#pragma unroll
        for (int nt = 0; nt < 16; nt++)
#pragma unroll
            for (int j = 0; j < 4; j++) acc[nt][j] = 0.f;

#pragma unroll 1
        for (int kc = 0; kc < 4; kc++) {
#pragma unroll 1
            for (int half = 0; half < 2; half++, s++) {
                CP_WAIT2();
                __syncthreads();
                if (s + 3 < NSTAGES) issueB(s + 3);
                CP_COMMIT();

                const unsigned stage = sb + SM_BRING + (s & 3) * 16384;
                const int npass = half ? 1 : 2;     // hi chunk: A_hi + A_lo; lo chunk: A_hi
#pragma unroll
                for (int ks = 0; ks < 4; ks++) {
                    unsigned B[8][4];
#pragma unroll
                    for (int p = 0; p < 8; p++) {
                        int brow = p * 16 + b_rowp;
                        ldsm4(B[p], stage + brow * 128 +
                              (((2 * ks + b_uoff) ^ (brow & 7)) << 4));
                    }
#pragma unroll
                    for (int pass = 0; pass < 2; pass++) {
                        if (pass >= npass) break;
                        const unsigned Abase = sb + (pass ? SM_A_LO : SM_A_HI);
                        const int u = kc * 8 + 2 * ks + a_uoff;
                        const int su = (u & 24) | ((u ^ a_row) & 7);
                        unsigned A[4];
                        ldsm4(A, Abase + a_row * 512 + (su << 4));
#pragma unroll
                        for (int nt = 0; nt < 16; nt++)
                            mma16816(acc[nt], A, &B[nt >> 1][(nt & 1) * 2]);
                    }
                }
            }
        }

        // ---- per-tile epilogue: fold into per-lane running best-2 ----
#pragma unroll
        for (int nt = 0; nt < 16; nt++) {
            const int n0 = t * TN + nt * 8 + 2 * (lane & 3);
            float2 cc = *(const float2*)(c2s + n0);
            float d0 = fmaf(-2.f, acc[nt][0], cc.x);
            float d1 = fmaf(-2.f, acc[nt][1], cc.y);
            float d2 = fmaf(-2.f, acc[nt][2], cc.x);
            float d3 = fmaf(-2.f, acc[nt][3], cc.y);
            upd2(k1lo, k2lo, ((ull)f2ord(d0) << 32) | (unsigned)n0);
            upd2(k1lo, k2lo, ((ull)f2ord(d1) << 32) | (unsigned)(n0 + 1));
            upd2(k1hi, k2hi, ((ull)f2ord(d2) << 32) | (unsigned)n0);
            upd2(k1hi, k2hi, ((ull)f2ord(d3) << 32) | (unsigned)(n0 + 1));
        }
    }

    // ---- cross-lane best-2 merge (4 lanes share each row) ----
#pragma unroll
    for (int off = 1; off <= 2; off <<= 1) {
        ull o1 = __shfl_xor_sync(0xFFFFFFFFu, k1lo, off);
        ull o2 = __shfl_xor_sync(0xFFFFFFFFu, k2lo, off);
        ull m2 = (k2lo < o2) ? k2lo : o2;
        ull mx = (k1lo > o1) ? k1lo : o1;
        k1lo = (k1lo < o1) ? k1lo : o1;
        k2lo = (mx < m2) ? mx : m2;
        o1 = __shfl_xor_sync(0xFFFFFFFFu, k1hi, off);
        o2 = __shfl_xor_sync(0xFFFFFFFFu, k2hi, off);
        m2 = (k2hi < o2) ? k2hi : o2;
        mx = (k1hi > o1) ? k1hi : o1;
        k1hi = (k1hi < o1) ? k1hi : o1;
        k2hi = (mx < m2) ? mx : m2;
    }

    if ((lane & 3) == 0) {
#pragma unroll
        for (int h = 0; h < 2; h++) {
            ull k1 = h ? k1hi : k1lo, k2 = h ? k2hi : k2lo;
            const int q = qbase + warp * 16 + (lane >> 2) + h * 8;
            unsigned i1 = (unsigned)(k1 & 0xFFFFFFFFu), i2 = (unsigned)(k2 & 0xFFFFFFFFu);
            unsigned o1 = (unsigned)(k1 >> 32), o2 = (unsigned)(k2 >> 32);
            float d1 = __uint_as_float((o1 & 0x80000000u) ? (o1 ^ 0x80000000u) : ~o1);
            float d2 = __uint_as_float((o2 & 0x80000000u) ? (o2 ^ 0x80000000u) : ~o2);
            unsigned win = i1;
            if (d2 - d1 < RESCORE_T) {
                const float* qv = x + (size_t)q * DD;
                float e1 = fmaf(-2.f, dot_exact(qv, cb + (size_t)i1 * DD), g_c2[i1]);
                float e2 = fmaf(-2.f, dot_exact(qv, cb + (size_t)i2 * DD), g_c2[i2]);
                if (e2 < e1 || (e2 == e1 && i2 < i1)) win = i2;
            }
            g_idx[q] = win;
        }
    }
}

// ---------------------------------------------------------------------------
// Output kernel: [x_recon | z_e | z_q | indices(float)]
// ---------------------------------------------------------------------------
__global__ void vq_out(const float* __restrict__ x, const float* __restrict__ cb,
                       float* __restrict__ out, int out_size) {
    const int BND = QN * DD, BND4 = BND / 4;
    int t = blockIdx.x * blockDim.x + threadIdx.x;
    if (t >= BND4) return;
    int q = t >> 6, c4 = t & 63;
    unsigned idx = g_idx[q];
    float4 zq = ((const float4*)cb)[(size_t)idx * (DD / 4) + c4];
    float4 xv = ((const float4*)x)[t];
    float4* o4 = (float4*)out;
    if (out_size >= BND)     o4[t] = zq;
    if (out_size >= 2 * BND) o4[BND4 + t] = xv;
    if (out_size >= 3 * BND) o4[2 * BND4 + t] = zq;
    if (c4 == 0 && out_size >= 3 * BND + QN) out[3 * BND + q] = (float)idx;
}

// ---------------------------------------------------------------------------
extern "C" void kernel_launch(void* const* d_in, const int* in_sizes, int n_in,
                              void* d_out, int out_size) {
    const float* x  = (const float*)d_in[0];
    const float* cb = (const float*)d_in[1];
    float* out = (float*)d_out;

    static int inited = 0;
    if (!inited) {
        cudaFuncSetAttribute(vq_main_mma, cudaFuncAttributeMaxDynamicSharedMemorySize,
                             SM_TOTAL);
        inited = 1;
    }

    const int TOT4 = (QN + KK) * DD / 4;
    vq_cvt<<<(TOT4 + NTHREADS - 1) / NTHREADS, NTHREADS>>>(x, cb);
    vq_c2k<<<(KK * 32 + NTHREADS - 1) / NTHREADS, NTHREADS>>>(cb);
    vq_main_mma<<<QN / TM, NTHREADS, SM_TOTAL>>>(x, cb);
    vq_out<<<(QN * DD / 4 + NTHREADS - 1) / NTHREADS, NTHREADS>>>(x, cb, out, out_size);
}

// round 4
// speedup vs baseline: 4.6322x; 2.3727x over previous
#include <cuda_runtime.h>
#include <cuda_bf16.h>
#include <cstdint>

// ---------------------------------------------------------------------------
// Problem constants
// ---------------------------------------------------------------------------
#define QN 16384      // B*N queries
#define DD 256        // dim
#define KK 8192       // codebook size
#define TM 128        // queries per block
#define TN 128        // codes per tile
#define NTILES (KK / TN)          // 64
#define NTHREADS 256
#define RESCORE_T 2.5f

// smem layout (bytes): A 64K | B ring 2x64K | c2 32K = 224KB
#define SM_A 0
#define SM_BRING 65536
#define SM_C2 196608
#define SM_TOTAL 229376
#define SM_SCR SM_BRING           // merge scratch reuses B ring after loop

typedef unsigned long long ull;

// ---------------------------------------------------------------------------
// device scratch (static: no allocations allowed)
// ---------------------------------------------------------------------------
__device__ __nv_bfloat16 g_x_hi[QN * DD];
__device__ __nv_bfloat16 g_cb_hi[KK * DD];
__device__ float    g_c2[KK];
__device__ unsigned g_idx[QN];

// ---------------------------------------------------------------------------
// PTX helpers (sm_80-baseline: legal on plain sm_103 target)
// ---------------------------------------------------------------------------
__device__ __forceinline__ unsigned smem_u32(const void* p) {
    unsigned a;
    asm("{ .reg .u64 t; cvta.to.shared.u64 t, %1; cvt.u32.u64 %0, t; }" : "=r"(a) : "l"(p));
    return a;
}
__device__ __forceinline__ void cp16(unsigned sdst, const void* g) {
    asm volatile("cp.async.cg.shared.global [%0], [%1], 16;" :: "r"(sdst), "l"(g));
}
#define CP_COMMIT() asm volatile("cp.async.commit_group;" ::: "memory")
#define CP_WAIT1()  asm volatile("cp.async.wait_group 1;" ::: "memory")

__device__ __forceinline__ void ldsm4(unsigned* r, unsigned addr) {
    asm volatile("ldmatrix.sync.aligned.m8n8.x4.shared.b16 {%0,%1,%2,%3}, [%4];"
                 : "=r"(r[0]), "=r"(r[1]), "=r"(r[2]), "=r"(r[3]) : "r"(addr));
}
__device__ __forceinline__ void mma16816(float* c, const unsigned* a, const unsigned* b) {
    asm volatile("mma.sync.aligned.m16n8k16.row.col.f32.bf16.bf16.f32 "
                 "{%0,%1,%2,%3}, {%4,%5,%6,%7}, {%8,%9}, {%0,%1,%2,%3};"
                 : "+f"(c[0]), "+f"(c[1]), "+f"(c[2]), "+f"(c[3])
                 : "r"(a[0]), "r"(a[1]), "r"(a[2]), "r"(a[3]), "r"(b[0]), "r"(b[1]));
}

__device__ __forceinline__ unsigned f2ord(float f) {
    unsigned u = __float_as_uint(f);
    return (u & 0x80000000u) ? ~u : (u | 0x80000000u);
}
__device__ __forceinline__ float decord(unsigned o) {
    unsigned u = (o & 0x80000000u) ? (o ^ 0x80000000u) : ~o;
    return __uint_as_float(u);
}
__device__ __forceinline__ void upd2(ull& a, ull& b, ull k) {
    if (k < a) { b = a; a = k; } else if (k < b) { b = k; }
}

// ---------------------------------------------------------------------------
// Kernel: fp32 -> bf16 (hi part only)
// ---------------------------------------------------------------------------
__device__ __forceinline__ unsigned pack2(__nv_bfloat16 a, __nv_bfloat16 b) {
    __nv_bfloat162 p = __halves2bfloat162(a, b);
    return *reinterpret_cast<unsigned*>(&p);
}

__global__ void vq_cvt(const float* __restrict__ x, const float* __restrict__ cb) {
    const int QX4 = QN * DD / 4, TOT4 = (QN + KK) * DD / 4;
    int t = blockIdx.x * blockDim.x + threadIdx.x;
    if (t >= TOT4) return;
    bool isx = t < QX4;
    float4 v = isx ? ((const float4*)x)[t] : ((const float4*)cb)[t - QX4];
    uint2 hp = make_uint2(pack2(__float2bfloat16_rn(v.x), __float2bfloat16_rn(v.y)),
                          pack2(__float2bfloat16_rn(v.z), __float2bfloat16_rn(v.w)));
    int o = isx ? t : t - QX4;
    ((uint2*)(isx ? g_x_hi : g_cb_hi))[o] = hp;
}

// ---------------------------------------------------------------------------
// Kernel: codebook row norms (one warp per row)
// ---------------------------------------------------------------------------
__global__ void vq_c2k(const float* __restrict__ cb) {
    int w = (blockIdx.x * blockDim.x + threadIdx.x) >> 5;
    int lane = threadIdx.x & 31;
    if (w >= KK) return;
    const float4* r = (const float4*)(cb + (size_t)w * DD);
    float s = 0.f;
#pragma unroll
    for (int j = 0; j < 2; j++) {
        float4 v = r[lane + 32 * j];
        s += v.x * v.x + v.y * v.y + v.z * v.z + v.w * v.w;
    }
#pragma unroll
    for (int o = 16; o; o >>= 1) s += __shfl_xor_sync(0xFFFFFFFFu, s, o);
    if (!lane) g_c2[w] = s;
}

// ---------------------------------------------------------------------------
// Main kernel: single-pass bf16 GEMM + best-2/slice argmin + exact rescore.
// grid = 128 blocks (128 queries each), 256 threads = 8 warps.
// Warp w: m64 rows [(w>>2)*64, +64), n32 cols [(w&3)*32, +32) of each tile.
// B double-buffered 64KB tiles via cp.async, 1-tile lookahead.
// ---------------------------------------------------------------------------
extern __shared__ char dsm[];

__device__ __forceinline__ float dot_exact(const float* a, const float* b) {
    float s0 = 0, s1 = 0, s2 = 0, s3 = 0;
    const float4* A = (const float4*)a;
    const float4* B = (const float4*)b;
#pragma unroll 16
    for (int i = 0; i < DD / 4; i++) {
        float4 u = A[i], w = B[i];
        s0 = fmaf(u.x, w.x, s0); s1 = fmaf(u.y, w.y, s1);
        s2 = fmaf(u.z, w.z, s2); s3 = fmaf(u.w, w.w, s3);
    }
    return (s0 + s1) + (s2 + s3);
}

__global__ void __launch_bounds__(NTHREADS, 1)
vq_main_mma(const float* __restrict__ x, const float* __restrict__ cb) {
    const unsigned sb = smem_u32(dsm);
    const int tid = threadIdx.x;
    const int warp = tid >> 5, lane = tid & 31;
    const int mg = warp >> 2, nw = warp & 3;
    const int qbase = blockIdx.x * TM;

    // ---- B tile load: 128 rows x 512B, 16B-unit XOR swizzle ----
    auto issueB = [&](int t) {
        const unsigned stage = sb + SM_BRING + (t & 1) * 65536;
        const __nv_bfloat16* src = g_cb_hi + (size_t)t * TN * DD;
#pragma unroll
        for (int i = 0; i < 16; i++) {
            int unit = tid + i * NTHREADS;          // 0..4095
            int row = unit >> 5, u = unit & 31;
            int su = (u & 24) | ((u ^ row) & 7);
            cp16(stage + row * 512 + (su << 4), src + row * DD + u * 8);
        }
    };

    // ---- resident A (swizzled) + c2 + B tile 0, one cp.async group ----
#pragma unroll
    for (int i = 0; i < 16; i++) {
        int unit = tid + i * NTHREADS;
        int row = unit >> 5, u = unit & 31;
        int su = (u & 24) | ((u ^ row) & 7);
        cp16(sb + SM_A + row * 512 + (su << 4),
             g_x_hi + (size_t)(qbase + row) * DD + u * 8);
    }
#pragma unroll
    for (int i = 0; i < 8; i++) {
        int l = i * NTHREADS + tid;                 // 0..2047
        cp16(sb + SM_C2 + l * 16, g_c2 + l * 4);
    }
    issueB(0);
    CP_COMMIT();

    // ldmatrix lane address components
    const int a_rowp = (lane & 7) + ((lane >> 3) & 1) * 8;
    const int a_uoff = (lane >> 4) & 1;
    const int b_rowp = (lane & 7) + ((lane >> 4) & 1) * 8;
    const int b_uoff = (lane >> 3) & 1;

    const float* c2s = (const float*)(dsm + SM_C2);

    ull k1[8], k2[8];                               // best-2 per covered row
#pragma unroll
    for (int i = 0; i < 8; i++) { k1[i] = ~0ull; k2[i] = ~0ull; }

#pragma unroll 1
    for (int t = 0; t < NTILES; t++) {
        __syncthreads();                            // buffer (t+1)&1 free
        if (t + 1 < NTILES) issueB(t + 1);
        CP_COMMIT();
        CP_WAIT1();                                 // tile t landed
        __syncthreads();

        const unsigned stage = sb + SM_BRING + (t & 1) * 65536;
        float acc[4][4][4];
#pragma unroll
        for (int a = 0; a < 4; a++)
#pragma unroll
            for (int b = 0; b < 4; b++)
#pragma unroll
                for (int c = 0; c < 4; c++) acc[a][b][c] = 0.f;

#pragma unroll
        for (int ks = 0; ks < 16; ks++) {
            unsigned Bf[2][4];
#pragma unroll
            for (int nt = 0; nt < 2; nt++) {
                int rb = nw * 32 + nt * 16 + b_rowp;
                int u = 2 * ks + b_uoff;
                int su = (u & 24) | ((u ^ rb) & 7);
                ldsm4(Bf[nt], stage + rb * 512 + (su << 4));
            }
#pragma unroll
            for (int mt = 0; mt < 4; mt++) {
                int ra = mg * 64 + mt * 16 + a_rowp;
                int u = 2 * ks + a_uoff;
                int su = (u & 24) | ((u ^ ra) & 7);
                unsigned Af[4];
                ldsm4(Af, sb + SM_A + ra * 512 + (su << 4));
                mma16816(acc[mt][0], Af, &Bf[0][0]);
                mma16816(acc[mt][1], Af, &Bf[0][2]);
                mma16816(acc[mt][2], Af, &Bf[1][0]);
                mma16816(acc[mt][3], Af, &Bf[1][2]);
            }
        }

        // ---- per-tile epilogue: fold into per-row best-2 ----
#pragma unroll
        for (int mt = 0; mt < 4; mt++) {
#pragma unroll
            for (int jj = 0; jj < 4; jj++) {
                const int n0 = t * TN + nw * 32 + jj * 8 + 2 * (lane & 3);
                float2 cc = *(const float2*)(c2s + n0);
                float d0 = fmaf(-2.f, acc[mt][jj][0], cc.x);
                float d1 = fmaf(-2.f, acc[mt][jj][1], cc.y);
                float d2 = fmaf(-2.f, acc[mt][jj][2], cc.x);
                float d3 = fmaf(-2.f, acc[mt][jj][3], cc.y);
                upd2(k1[2 * mt],     k2[2 * mt],     ((ull)f2ord(d0) << 32) | (unsigned)n0);
                upd2(k1[2 * mt],     k2[2 * mt],     ((ull)f2ord(d1) << 32) | (unsigned)(n0 + 1));
                upd2(k1[2 * mt + 1], k2[2 * mt + 1], ((ull)f2ord(d2) << 32) | (unsigned)n0);
                upd2(k1[2 * mt + 1], k2[2 * mt + 1], ((ull)f2ord(d3) << 32) | (unsigned)(n0 + 1));
            }
        }
    }

    // ---- merge best-2 across the 4 lanes sharing each row ----
#pragma unroll
    for (int i = 0; i < 8; i++) {
#pragma unroll
        for (int off = 1; off <= 2; off <<= 1) {
            ull o1 = __shfl_xor_sync(0xFFFFFFFFu, k1[i], off);
            ull o2 = __shfl_xor_sync(0xFFFFFFFFu, k2[i], off);
            ull m2 = (k2[i] < o2) ? k2[i] : o2;
            ull mx = (k1[i] > o1) ? k1[i] : o1;
            k1[i] = (k1[i] < o1) ? k1[i] : o1;
            k2[i] = (mx < m2) ? mx : m2;
        }
    }

    __syncthreads();                                // compute fully done
    if ((lane & 3) == 0) {
        ulonglong2* scr = (ulonglong2*)(dsm + SM_SCR);
#pragma unroll
        for (int s = 0; s < 8; s++) {
            int mt = s >> 1, rh = s & 1;
            int row = mg * 64 + mt * 16 + (lane >> 2) + rh * 8;
            scr[row * 4 + nw] = make_ulonglong2(k1[s], k2[s]);
        }
    }
    __syncthreads();

    // ---- final per-query: merge 4 slices (8 cands), rescore near-ties ----
    if (tid < TM) {
        const int row = tid;
        const ulonglong2* scr = (const ulonglong2*)(dsm + SM_SCR);
        ull c8[8];
#pragma unroll
        for (int i = 0; i < 4; i++) {
            ulonglong2 v = scr[row * 4 + i];
            c8[2 * i] = v.x; c8[2 * i + 1] = v.y;
        }
        ull kmin = c8[0];
#pragma unroll
        for (int i = 1; i < 8; i++) kmin = (c8[i] < kmin) ? c8[i] : kmin;
        float dmin = decord((unsigned)(kmin >> 32));
        unsigned win = (unsigned)kmin;

        unsigned cand[8]; int nc = 0;
#pragma unroll
        for (int i = 0; i < 8; i++) {
            float d = decord((unsigned)(c8[i] >> 32));
            if (d - dmin < RESCORE_T) cand[nc++] = (unsigned)c8[i];
        }
        if (nc > 1) {
            const float* qv = x + (size_t)(qbase + row) * DD;
            float be = 3.4e38f; unsigned bi = 0xFFFFFFFFu;
            for (int j = 0; j < nc; j++) {
                unsigned i = cand[j];
                float e = fmaf(-2.f, dot_exact(qv, cb + (size_t)i * DD), c2s[i]);
                if (e < be || (e == be && i < bi)) { be = e; bi = i; }
            }
            win = bi;
        }
        g_idx[qbase + row] = win;
    }
}

// ---------------------------------------------------------------------------
// Output kernel: [x_recon | z_e | z_q | indices(float)]
// ---------------------------------------------------------------------------
__global__ void vq_out(const float* __restrict__ x, const float* __restrict__ cb,
                       float* __restrict__ out, int out_size) {
    const int BND = QN * DD, BND4 = BND / 4;
    int t = blockIdx.x * blockDim.x + threadIdx.x;
    if (t >= BND4) return;
    int q = t >> 6, c4 = t & 63;
    unsigned idx = g_idx[q];
    float4 zq = ((const float4*)cb)[(size_t)idx * (DD / 4) + c4];
    float4 xv = ((const float4*)x)[t];
    float4* o4 = (float4*)out;
    if (out_size >= BND)     o4[t] = zq;
    if (out_size >= 2 * BND) o4[BND4 + t] = xv;
    if (out_size >= 3 * BND) o4[2 * BND4 + t] = zq;
    if (c4 == 0 && out_size >= 3 * BND + QN) out[3 * BND + q] = (float)idx;
}

// ---------------------------------------------------------------------------
extern "C" void kernel_launch(void* const* d_in, const int* in_sizes, int n_in,
                              void* d_out, int out_size) {
    const float* x  = (const float*)d_in[0];
    const float* cb = (const float*)d_in[1];
    float* out = (float*)d_out;

    static int inited = 0;
    if (!inited) {
        cudaFuncSetAttribute(vq_main_mma, cudaFuncAttributeMaxDynamicSharedMemorySize,
                             SM_TOTAL);
        inited = 1;
    }

    const int TOT4 = (QN + KK) * DD / 4;
    vq_cvt<<<(TOT4 + NTHREADS - 1) / NTHREADS, NTHREADS>>>(x, cb);
    vq_c2k<<<(KK * 32 + NTHREADS - 1) / NTHREADS, NTHREADS>>>(cb);
    vq_main_mma<<<QN / TM, NTHREADS, SM_TOTAL>>>(x, cb);
    vq_out<<<(QN * DD / 4 + NTHREADS - 1) / NTHREADS, NTHREADS>>>(x, cb, out, out_size);
}